// round 15
// baseline (speedup 1.0000x reference)
#include <cuda_runtime.h>
#include <cuda_bf16.h>
#include <math.h>

#define NN 4096
#define KN 48
#define CC 128
#define EC 384
#define HD 512

// ---------------- scratch (device globals: allocation-free) ----------------
__device__ float g_node_pre[NN * CC];   // node @ W1a^T + b_m1
__device__ float g_S[NN * CC];          // sum_k attn * h2
__device__ float g_A[NN];               // sum_k attn
__device__ unsigned g_Wp1[6 * 4096];    // W1b, PAIR layout, 6 k-tiles of 32 kk
__device__ unsigned g_Wp2[2 * 4096];    // W2,  PAIR layout, 2 k-tiles of 32 kk
__device__ unsigned g_Wp3[64 * 128];    // W3    packed bf16x2: [kk][d]   (old style)
__device__ unsigned g_WpD1[256 * 128];  // Wd1   packed: [t*64+kk][h]     (old style)
__device__ unsigned g_WpD2[256 * 128];  // Wd2   packed: [kt*64+kk][c]    (old style)

__device__ __forceinline__ float gelu_f(float x) {
    return 0.5f * x * (1.0f + erff(x * 0.70710678118654752440f));
}

__device__ __forceinline__ unsigned pk(float a, float b) {
    __nv_bfloat162 t = __floats2bfloat162_rn(a, b);
    return *(unsigned*)&t;
}

// pair-layout column permutation: kk -> col' within each 8-word k-group
__device__ __host__ __forceinline__ int permc(int kk) {
    return (kk & ~7) + 2 * (kk & 3) + ((kk >> 2) & 1);
}

__device__ __forceinline__ void mma_bf16(float c[4], const unsigned a[4], const unsigned b[2]) {
    asm volatile(
        "mma.sync.aligned.m16n8k16.row.col.f32.bf16.bf16.f32 "
        "{%0,%1,%2,%3},{%4,%5,%6,%7},{%8,%9},{%0,%1,%2,%3};\n"
        : "+f"(c[0]), "+f"(c[1]), "+f"(c[2]), "+f"(c[3])
        : "r"(a[0]), "r"(a[1]), "r"(a[2]), "r"(a[3]), "r"(b[0]), "r"(b[1]));
}

#define CP_ASYNC16(dst, src) \
    asm volatile("cp.async.cg.shared.global [%0], [%1], 16;" :: "r"(dst), "l"(src))
#define CP_COMMIT() asm volatile("cp.async.commit_group;" ::)
#define CP_WAIT0()  asm volatile("cp.async.wait_group 0;" ::)

// 32xN(=128)xK(=128) block-GEMM step (OLD layouts; used by kt_mma only)
__device__ __forceinline__ void gemm32(const unsigned* sA, int astride,
                                       const unsigned* sB, int mg, int ng,
                                       int lane, float acc[4][4]) {
    const int g = lane >> 2, q = lane & 3;
#pragma unroll
    for (int s = 0; s < 8; ++s) {
        unsigned a[4], bf[4][2];
        const unsigned* base = sA + (mg * 16 + g) * astride + s * 8 + q;
        a[0] = base[0];
        a[1] = base[8 * astride];
        a[2] = base[4];
        a[3] = base[8 * astride + 4];
#pragma unroll
        for (int t = 0; t < 4; ++t) {
            int n = ng * 32 + t * 8 + g;
            bf[t][0] = sB[(s * 8 + q) * 136 + n];
            bf[t][1] = sB[(s * 8 + 4 + q) * 136 + n];
        }
#pragma unroll
        for (int t = 0; t < 4; ++t) mma_bf16(acc[t], a, bf[t]);
    }
}

// =================== Kprep: pack ALL weights to bf16x2 =====================
// g_Wp1/g_Wp2: PAIR layout. Per 32-kk tile: word = s*1024 + n*8 + q*2 + which,
// holding bf16x2 of k-pair kk = tile*32 + s*8 + q + 4*which.
__global__ __launch_bounds__(256)
void k_prep(const float* __restrict__ W1, const float* __restrict__ W2,
            const float* __restrict__ W3, const float* __restrict__ Wd1,
            const float* __restrict__ Wd2) {
    int idx = blockIdx.x * 256 + threadIdx.x;
    if (idx < 24576) {                       // g_Wp1: 6 tiles x 4096
        int kt = idx >> 12;
        int r = idx & 4095;
        int s = r >> 10;
        int n = (r >> 3) & 127;
        int q = (r >> 1) & 3;
        int which = r & 1;
        int kk = kt * 32 + s * 8 + q + 4 * which;
        g_Wp1[idx] = pk(W1[(size_t)n * 512 + 128 + 2 * kk],
                        W1[(size_t)n * 512 + 128 + 2 * kk + 1]);
    } else if (idx < 32768) {                // g_Wp2: 2 tiles x 4096
        int j = idx - 24576;
        int kt = j >> 12;
        int r = j & 4095;
        int s = r >> 10;
        int n = (r >> 3) & 127;
        int q = (r >> 1) & 3;
        int which = r & 1;
        int kk = kt * 32 + s * 8 + q + 4 * which;
        g_Wp2[j] = pk(W2[(size_t)n * 128 + 2 * kk],
                      W2[(size_t)n * 128 + 2 * kk + 1]);
    } else if (idx < 40960) {                // g_Wp3: 64*128 (old style)
        int j = idx - 32768;
        int kk = j >> 7, d = j & 127;
        g_Wp3[j] = pk(W3[(size_t)d * 128 + 2 * kk],
                      W3[(size_t)d * 128 + 2 * kk + 1]);
    } else if (idx < 73728) {                // g_WpD1: 256*128 (old style)
        int j = idx - 40960;
        int row = j >> 7, hh = j & 127;
        int t = row >> 6, kk = row & 63;
        g_WpD1[j] = pk(Wd1[(size_t)(t * 128 + hh) * 128 + 2 * kk],
                       Wd1[(size_t)(t * 128 + hh) * 128 + 2 * kk + 1]);
    } else if (idx < 106496) {               // g_WpD2: 256*128 (old style)
        int j = idx - 73728;
        int row = j >> 7, c = j & 127;
        int kt = row >> 6, kk = row & 63;
        g_WpD2[j] = pk(Wd2[(size_t)c * 512 + kt * 128 + 2 * kk],
                       Wd2[(size_t)c * 512 + kt * 128 + 2 * kk + 1]);
    }
}

// ======================= K0: node_pre = node @ W1a^T + b1 ==================
__global__ __launch_bounds__(256)
void k0_node_pre(const float* __restrict__ node, const float* __restrict__ W1,
                 const float* __restrict__ b1) {
    extern __shared__ float sm[];
    float* sX = sm;           // 32*128
    float* sW = sm + 4096;    // 128*128  sW[k][c] = W1[c*512 + k]
    const int tid = threadIdx.x, tx = tid & 15, ty = tid >> 4;
    const int n0 = blockIdx.x * 32;

#pragma unroll
    for (int m = 0; m < 4; ++m) {
        int f4 = tid + 256 * m;
        int r = f4 >> 5, c4 = f4 & 31;
        *(float4*)(sX + r * 128 + c4 * 4) =
            *(const float4*)(node + (size_t)(n0 + r) * 128 + c4 * 4);
    }
#pragma unroll
    for (int m = 0; m < 16; ++m) {
        int idx = tid + 256 * m;
        int c = idx & 127, k4 = idx >> 7;
        float4 v = *(const float4*)(W1 + (size_t)c * 512 + k4 * 4);
        sW[(k4 * 4 + 0) * 128 + c] = v.x;
        sW[(k4 * 4 + 1) * 128 + c] = v.y;
        sW[(k4 * 4 + 2) * 128 + c] = v.z;
        sW[(k4 * 4 + 3) * 128 + c] = v.w;
    }
    __syncthreads();

    float acc[2][8] = {};
#pragma unroll
    for (int kk = 0; kk < 128; kk += 4) {
        float a[2][4];
#pragma unroll
        for (int i = 0; i < 2; ++i) {
            float4 t = *(float4*)(sX + (ty + 16 * i) * 128 + kk);
            a[i][0] = t.x; a[i][1] = t.y; a[i][2] = t.z; a[i][3] = t.w;
        }
#pragma unroll
        for (int q = 0; q < 4; ++q) {
            float4 b0 = *(float4*)(sW + (kk + q) * 128 + tx * 8);
            float4 b1v = *(float4*)(sW + (kk + q) * 128 + tx * 8 + 4);
            float bb[8] = {b0.x, b0.y, b0.z, b0.w, b1v.x, b1v.y, b1v.z, b1v.w};
#pragma unroll
            for (int i = 0; i < 2; ++i)
#pragma unroll
                for (int j = 0; j < 8; ++j) acc[i][j] += a[i][q] * bb[j];
        }
    }
#pragma unroll
    for (int i = 0; i < 2; ++i) {
        int r = n0 + ty + 16 * i;
#pragma unroll
        for (int j = 0; j < 8; ++j) {
            int c = tx * 8 + j;
            g_node_pre[(size_t)r * 128 + c] = acc[i][j] + b1[c];
        }
    }
}

// ================ K1: per-node-pair edge message kernel (bf16 MMA) =========
// Pair-packed fragments: A via LDS.64 (perm cols, stride 40/72),
// B via LDS.64 (pair layout). Double-buffered k-tiles as in R14.
#define A0_OFF 0            // 96*40
#define A1_OFF 3840
#define B0_OFF 7680         // 4096 (pair tile)
#define B1_OFF 11776
#define SH1_OFF 15872       // 96*72
#define NP_OFF 22784        // 256 f
#define AT_OFF 23040        // 128 f
#define B2A_OFF 23168       // 128 f
#define S1_WORDS 23296

__global__ __launch_bounds__(256, 2)
void k1_edges(const float* __restrict__ edge, const float* __restrict__ attn,
              const float* __restrict__ b2) {
    extern __shared__ unsigned smu[];
    unsigned* sH = smu + SH1_OFF;
    float* sNP = (float*)(smu + NP_OFF);
    float* sAt = (float*)(smu + AT_OFF);
    float* sb2 = (float*)(smu + B2A_OFF);
    const unsigned smem_base = (unsigned)__cvta_generic_to_shared(smu);

    const int tid = threadIdx.x;
    const int lane = tid & 31, wid = tid >> 5;
    const int mg = wid >> 2;
    const int ng = wid & 3;
    const int g = lane >> 2, q = lane & 3;
    const int n0 = blockIdx.x * 2;
    const float* eb = edge + (size_t)n0 * (KN * EC);

    sNP[tid] = g_node_pre[(size_t)n0 * 128 + tid];
    if (tid < 96) sAt[tid] = attn[(size_t)n0 * KN + tid];
    if (tid < 128) sb2[tid] = b2[tid];

    // ---- prologue: tile 0 ----
#pragma unroll
    for (int m = 0; m < 6; ++m) {
        int f = tid + 256 * m;
        int row = f >> 4, c4 = f & 15;
        float4 v = *(const float4*)(eb + (size_t)row * EC + c4 * 4);
        int k2 = c4 * 2;
        smu[A0_OFF + row * 40 + permc(k2)] = pk(v.x, v.y);
        smu[A0_OFF + row * 40 + permc(k2 + 1)] = pk(v.z, v.w);
    }
#pragma unroll
    for (int m = 0; m < 4; ++m) {
        int f = tid + 256 * m;                 // 0..1023
        CP_ASYNC16(smem_base + (B0_OFF + f * 4) * 4, g_Wp1 + f * 4);
    }
    CP_COMMIT();
    CP_WAIT0();
    __syncthreads();

    float acc[3][4][4] = {};
    float4 st[6];

    // ---------------- GEMM1b: 6 double-buffered k-tiles of 64 --------------
    for (int kt = 0; kt < 6; ++kt) {
        const unsigned* sA = smu + ((kt & 1) ? A1_OFF : A0_OFF);
        const unsigned* sB = smu + ((kt & 1) ? B1_OFF : B0_OFF);
        if (kt < 5) {
#pragma unroll
            for (int m = 0; m < 6; ++m) {
                int f = tid + 256 * m;
                int row = f >> 4, c4 = f & 15;
                st[m] = *(const float4*)(eb + (size_t)row * EC + (kt + 1) * 64 + c4 * 4);
            }
            unsigned bdst = smem_base + (((kt + 1) & 1) ? B1_OFF : B0_OFF) * 4;
#pragma unroll
            for (int m = 0; m < 4; ++m) {
                int f = tid + 256 * m;
                CP_ASYNC16(bdst + f * 16, g_Wp1 + (size_t)(kt + 1) * 4096 + f * 4);
            }
            CP_COMMIT();
        } else {
            // prefetch W2 pair-tile 0 (kk 0..31) into B0 (free since kt=4)
#pragma unroll
            for (int m = 0; m < 4; ++m) {
                int f = tid + 256 * m;
                CP_ASYNC16(smem_base + (B0_OFF + f * 4) * 4, g_Wp2 + f * 4);
            }
            CP_COMMIT();
        }
#pragma unroll
        for (int s = 0; s < 4; ++s) {
            unsigned a[3][4];
            uint2 bf[4];
#pragma unroll
            for (int mi = 0; mi < 3; ++mi) {
                const unsigned* base = sA + (mg * 48 + mi * 16 + g) * 40 + s * 8 + 2 * q;
                uint2 va = *(const uint2*)base;
                uint2 vb = *(const uint2*)(base + 8 * 40);
                a[mi][0] = va.x; a[mi][2] = va.y;
                a[mi][1] = vb.x; a[mi][3] = vb.y;
            }
#pragma unroll
            for (int t = 0; t < 4; ++t)
                bf[t] = *(const uint2*)(sB + s * 1024 + (ng * 32 + t * 8 + g) * 8 + q * 2);
#pragma unroll
            for (int mi = 0; mi < 3; ++mi)
#pragma unroll
                for (int t = 0; t < 4; ++t) mma_bf16(acc[mi][t], a[mi], &bf[t].x);
        }
        if (kt < 5) {
            unsigned* dA = smu + (((kt + 1) & 1) ? A1_OFF : A0_OFF);
#pragma unroll
            for (int m = 0; m < 6; ++m) {
                int f = tid + 256 * m;
                int row = f >> 4, c4 = f & 15;
                int k2 = c4 * 2;
                dA[row * 40 + permc(k2)] = pk(st[m].x, st[m].y);
                dA[row * 40 + permc(k2 + 1)] = pk(st[m].z, st[m].w);
            }
            CP_WAIT0();
        }
        __syncthreads();
    }

    // ---- epilogue 1: kick W2 pair-tile 1 -> B1; h1 = gelu(node_pre+acc) ----
#pragma unroll
    for (int m = 0; m < 4; ++m) {
        int f = tid + 256 * m;
        CP_ASYNC16(smem_base + (B1_OFF + f * 4) * 4, g_Wp2 + 4096 + f * 4);
    }
    CP_COMMIT();
#pragma unroll
    for (int mi = 0; mi < 3; ++mi) {
        int r0 = mg * 48 + mi * 16 + g;
#pragma unroll
        for (int t = 0; t < 4; ++t) {
            int c = ng * 32 + t * 8 + 2 * q;
            float np0 = sNP[mg * 128 + c], np1 = sNP[mg * 128 + c + 1];
            unsigned lo = pk(gelu_f(acc[mi][t][0] + np0), gelu_f(acc[mi][t][1] + np1));
            unsigned hi = pk(gelu_f(acc[mi][t][2] + np0), gelu_f(acc[mi][t][3] + np1));
            int pw = permc(ng * 16 + t * 4 + q);
            sH[r0 * 72 + pw] = lo;
            sH[(r0 + 8) * 72 + pw] = hi;
            acc[mi][t][0] = acc[mi][t][1] = acc[mi][t][2] = acc[mi][t][3] = 0.f;
        }
    }
    if (tid < 2) {
        float s = 0.f;
#pragma unroll
        for (int k = 0; k < KN; ++k) s += sAt[tid * KN + k];
        g_A[n0 + tid] = s;
    }
    CP_WAIT0();
    __syncthreads();

    // ---------------- GEMM2: h1 @ W2^T (8 k16 steps, B0 then B1) -----------
#pragma unroll
    for (int s = 0; s < 8; ++s) {
        const unsigned* sBp = smu + ((s < 4) ? B0_OFF : B1_OFF);
        int ss = s & 3;
        unsigned a[3][4];
        uint2 bf[4];
#pragma unroll
        for (int mi = 0; mi < 3; ++mi) {
            const unsigned* base = sH + (mg * 48 + mi * 16 + g) * 72 + s * 8 + 2 * q;
            uint2 va = *(const uint2*)base;
            uint2 vb = *(const uint2*)(base + 8 * 72);
            a[mi][0] = va.x; a[mi][2] = va.y;
            a[mi][1] = vb.x; a[mi][3] = vb.y;
        }
#pragma unroll
        for (int t = 0; t < 4; ++t)
            bf[t] = *(const uint2*)(sBp + ss * 1024 + (ng * 32 + t * 8 + g) * 8 + q * 2);
#pragma unroll
        for (int mi = 0; mi < 3; ++mi)
#pragma unroll
            for (int t = 0; t < 4; ++t) mma_bf16(acc[mi][t], a[mi], &bf[t].x);
    }

    // ---- epilogue 2: gelu(+b2), attn-weighted reduce over the 48 rows -----
#pragma unroll
    for (int t = 0; t < 4; ++t) {
        int c = ng * 32 + t * 8 + 2 * q;
        float bc0 = sb2[c], bc1 = sb2[c + 1];
        float p0 = 0.f, p1 = 0.f;
#pragma unroll
        for (int mi = 0; mi < 3; ++mi) {
            int r0 = mi * 16 + g;
            float w0 = sAt[mg * 48 + r0];
            float w1 = sAt[mg * 48 + r0 + 8];
            p0 += w0 * gelu_f(acc[mi][t][0] + bc0) + w1 * gelu_f(acc[mi][t][2] + bc0);
            p1 += w0 * gelu_f(acc[mi][t][1] + bc1) + w1 * gelu_f(acc[mi][t][3] + bc1);
        }
#pragma unroll
        for (int off = 16; off >= 4; off >>= 1) {
            p0 += __shfl_xor_sync(0xffffffffu, p0, off);
            p1 += __shfl_xor_sync(0xffffffffu, p1, off);
        }
        if (lane < 4) {
            int cc = ng * 32 + t * 8 + 2 * lane;
            g_S[(size_t)(n0 + mg) * 128 + cc] = p0;
            g_S[(size_t)(n0 + mg) * 128 + cc + 1] = p1;
        }
    }
}

// ============== KT: fused bf16-MMA tail, 32 nodes/block, grid 128 ==========
#define T_SB   0
#define T_AB   8704
#define T_HB   10880
#define T_RES  19200
#define T_SX   23424
#define T_RED  27648
#define T_WORDS 28672

__global__ __launch_bounds__(256)
void kt_mma(const float* __restrict__ node, const float* __restrict__ b3,
            const float* __restrict__ g1, const float* __restrict__ be1,
            const float* __restrict__ bd1, const float* __restrict__ bd2,
            const float* __restrict__ g2, const float* __restrict__ be2,
            const float* __restrict__ maskp, float* __restrict__ out) {
    extern __shared__ unsigned smu[];
    unsigned* sB = smu + T_SB;
    unsigned* sAb = smu + T_AB;
    unsigned* sHb = smu + T_HB;
    float* sRes = (float*)(smu + T_RES);
    float* sX = (float*)(smu + T_SX);
    float* sRed = (float*)(smu + T_RED);

    const int tid = threadIdx.x;
    const int lane = tid & 31, wid = tid >> 5;
    const int mg = wid >> 2, ng = wid & 3;
    const int g = lane >> 2, q = lane & 3;
    const int tx = tid & 15, ty = tid >> 4;
    const int n0 = blockIdx.x * 32;

#pragma unroll
    for (int m = 0; m < 4; ++m) {
        int f = tid + 256 * m;
        int row = f >> 5, c4 = f & 31;
        float4 v = *(const float4*)(g_S + (size_t)(n0 + row) * 128 + c4 * 4);
        *(uint2*)(sAb + row * 68 + c4 * 2) = make_uint2(pk(v.x, v.y), pk(v.z, v.w));
    }
#pragma unroll
    for (int m = 0; m < 8; ++m) {
        int f = tid + 256 * m;
        int kk = f >> 5, c4 = f & 31;
        *(uint4*)(sB + kk * 136 + c4 * 4) =
            *(const uint4*)(g_Wp3 + (size_t)kk * 128 + c4 * 4);
    }
    __syncthreads();

    float acc[4][4] = {};
    gemm32(sAb, 68, sB, mg, ng, lane, acc);
    {
        int r0 = mg * 16 + g;
#pragma unroll
        for (int t = 0; t < 4; ++t) {
            int c = ng * 32 + t * 8 + 2 * q;
            sRes[r0 * 132 + c] = acc[t][0];
            sRes[r0 * 132 + c + 1] = acc[t][1];
            sRes[(r0 + 8) * 132 + c] = acc[t][2];
            sRes[(r0 + 8) * 132 + c + 1] = acc[t][3];
        }
    }
    __syncthreads();

    float xv[2][8];
#pragma unroll
    for (int i = 0; i < 2; ++i) {
        int r = ty + 16 * i, n = n0 + r;
        float As = g_A[n];
        float s = 0.f, qs = 0.f;
#pragma unroll
        for (int j = 0; j < 8; ++j) {
            int c = tx * 8 + j;
            float v = node[(size_t)n * 128 + c] +
                      (sRes[r * 132 + c] + As * b3[c]) * (1.0f / 30.0f);
            xv[i][j] = v; s += v; qs += v * v;
        }
        sRed[r * 16 + tx] = s;
        sRed[512 + r * 16 + tx] = qs;
    }
    __syncthreads();
#pragma unroll
    for (int i = 0; i < 2; ++i) {
        int r = ty + 16 * i;
        float s = 0.f, qs = 0.f;
#pragma unroll
        for (int t = 0; t < 16; ++t) {
            s += sRed[r * 16 + t];
            qs += sRed[512 + r * 16 + t];
        }
        float mu = s * (1.0f / 128.0f);
        float var = qs * (1.0f / 128.0f) - mu * mu;
        float rs = rsqrtf(var + 1e-5f);
        float o[8];
#pragma unroll
        for (int j = 0; j < 8; ++j) {
            int c = tx * 8 + j;
            o[j] = (xv[i][j] - mu) * rs * g1[c] + be1[c];
            sX[r * 132 + c] = o[j];
        }
#pragma unroll
        for (int m = 0; m < 4; ++m)
            sAb[r * 68 + tx * 4 + m] = pk(o[2 * m], o[2 * m + 1]);
    }

    for (int t = 0; t < 4; ++t) {
        __syncthreads();
#pragma unroll
        for (int m = 0; m < 8; ++m) {
            int f = tid + 256 * m;
            int kk = f >> 5, c4 = f & 31;
            *(uint4*)(sB + kk * 136 + c4 * 4) =
                *(const uint4*)(g_WpD1 + (size_t)(t * 64 + kk) * 128 + c4 * 4);
        }
        __syncthreads();
        float a2[4][4] = {};
        gemm32(sAb, 68, sB, mg, ng, lane, a2);
        int r0 = mg * 16 + g;
#pragma unroll
        for (int tp = 0; tp < 4; ++tp) {
            int cl = ng * 32 + tp * 8 + 2 * q;
            int h = t * 128 + cl;
            float bb0 = bd1[h], bb1 = bd1[h + 1];
            unsigned lo = pk(gelu_f(a2[tp][0] + bb0), gelu_f(a2[tp][1] + bb1));
            unsigned hi = pk(gelu_f(a2[tp][2] + bb0), gelu_f(a2[tp][3] + bb1));
            int widx = t * 64 + ng * 16 + tp * 4 + q;
            sHb[r0 * 260 + widx] = lo;
            sHb[(r0 + 8) * 260 + widx] = hi;
        }
    }

    float acc3[4][4] = {};
    for (int kt = 0; kt < 4; ++kt) {
        __syncthreads();
#pragma unroll
        for (int m = 0; m < 8; ++m) {
            int f = tid + 256 * m;
            int kk = f >> 5, c4 = f & 31;
            *(uint4*)(sB + kk * 136 + c4 * 4) =
                *(const uint4*)(g_WpD2 + (size_t)(kt * 64 + kk) * 128 + c4 * 4);
        }
        __syncthreads();
        gemm32(sHb + kt * 64, 260, sB, mg, ng, lane, acc3);
    }
    {
        int r0 = mg * 16 + g;
#pragma unroll
        for (int t = 0; t < 4; ++t) {
            int c = ng * 32 + t * 8 + 2 * q;
            sRes[r0 * 132 + c] = acc3[t][0];
            sRes[r0 * 132 + c + 1] = acc3[t][1];
            sRes[(r0 + 8) * 132 + c] = acc3[t][2];
            sRes[(r0 + 8) * 132 + c + 1] = acc3[t][3];
        }
    }
    __syncthreads();

    float vv[2][8];
#pragma unroll
    for (int i = 0; i < 2; ++i) {
        int r = ty + 16 * i;
        float s = 0.f, qs = 0.f;
#pragma unroll
        for (int j = 0; j < 8; ++j) {
            int c = tx * 8 + j;
            float v = sX[r * 132 + c] + sRes[r * 132 + c] + bd2[c];
            vv[i][j] = v; s += v; qs += v * v;
        }
        sRed[r * 16 + tx] = s;
        sRed[512 + r * 16 + tx] = qs;
    }
    __syncthreads();
#pragma unroll
    for (int i = 0; i < 2; ++i) {
        int r = ty + 16 * i, n = n0 + r;
        float s = 0.f, qs = 0.f;
#pragma unroll
        for (int t = 0; t < 16; ++t) {
            s += sRed[r * 16 + t];
            qs += sRed[512 + r * 16 + t];
        }
        float mu = s * (1.0f / 128.0f);
        float var = qs * (1.0f / 128.0f) - mu * mu;
        float rs = rsqrtf(var + 1e-5f);
        float mk = maskp[n];
        float o[8];
#pragma unroll
        for (int j = 0; j < 8; ++j) {
            int c = tx * 8 + j;
            o[j] = mk * ((vv[i][j] - mu) * rs * g2[c] + be2[c]);
        }
        *(float4*)(out + (size_t)n * 128 + tx * 8) = make_float4(o[0], o[1], o[2], o[3]);
        *(float4*)(out + (size_t)n * 128 + tx * 8 + 4) = make_float4(o[4], o[5], o[6], o[7]);
    }
}

// ============================== launch =====================================
extern "C" void kernel_launch(void* const* d_in, const int* in_sizes, int n_in,
                              void* d_out, int out_size) {
    const float* node = (const float*)d_in[0];
    const float* edge = (const float*)d_in[1];
    const float* mask = (const float*)d_in[2];
    const float* attn = (const float*)d_in[3];
    const float* W1   = (const float*)d_in[4];
    const float* b1   = (const float*)d_in[5];
    const float* W2   = (const float*)d_in[6];
    const float* b2   = (const float*)d_in[7];
    const float* W3   = (const float*)d_in[8];
    const float* b3   = (const float*)d_in[9];
    const float* g1   = (const float*)d_in[10];
    const float* be1  = (const float*)d_in[11];
    const float* Wd1  = (const float*)d_in[12];
    const float* bd1  = (const float*)d_in[13];
    const float* Wd2  = (const float*)d_in[14];
    const float* bd2  = (const float*)d_in[15];
    const float* g2   = (const float*)d_in[16];
    const float* be2  = (const float*)d_in[17];
    float* out = (float*)d_out;

    const size_t s0 = (size_t)(4096 + 16384) * sizeof(float);
    const size_t s1 = (size_t)S1_WORDS * sizeof(unsigned);
    const size_t st = (size_t)T_WORDS * sizeof(unsigned);

    cudaFuncSetAttribute(k0_node_pre, cudaFuncAttributeMaxDynamicSharedMemorySize, (int)s0);
    cudaFuncSetAttribute(k1_edges,    cudaFuncAttributeMaxDynamicSharedMemorySize, (int)s1);
    cudaFuncSetAttribute(kt_mma,      cudaFuncAttributeMaxDynamicSharedMemorySize, (int)st);

    k_prep<<<416, 256>>>(W1, W2, W3, Wd1, Wd2);
    k0_node_pre<<<NN / 32, 256, s0>>>(node, W1, b1);
    k1_edges<<<NN / 2, 256, s1>>>(edge, attn, b2);
    kt_mma<<<NN / 32, 256, st>>>(node, b3, g1, be1, bd1, bd2, g2, be2, mask, out);
}

// round 16
// speedup vs baseline: 1.0120x; 1.0120x over previous
#include <cuda_runtime.h>
#include <cuda_bf16.h>
#include <math.h>

#define NN 4096
#define KN 48
#define CC 128
#define EC 384
#define HD 512

// ---------------- scratch (device globals: allocation-free) ----------------
__device__ float g_node_pre[NN * CC];   // node @ W1a^T + b_m1
__device__ float g_S[NN * CC];          // sum_k attn * h2
__device__ float g_A[NN];               // sum_k attn
__device__ unsigned g_Wp1[6 * 4096];    // W1b, PAIR layout, 6 k-tiles of 32 kk
__device__ unsigned g_Wp2[2 * 4096];    // W2,  PAIR layout, 2 k-tiles of 32 kk
__device__ unsigned g_Wp3[64 * 128];    // W3    packed bf16x2: [kk][d]   (old style)
__device__ unsigned g_WpD1[256 * 128];  // Wd1   packed: [t*64+kk][h]     (old style)
__device__ unsigned g_WpD2[256 * 128];  // Wd2   packed: [kt*64+kk][c]    (old style)

__device__ __forceinline__ float gelu_f(float x) {
    return 0.5f * x * (1.0f + erff(x * 0.70710678118654752440f));
}

__device__ __forceinline__ unsigned pk(float a, float b) {
    __nv_bfloat162 t = __floats2bfloat162_rn(a, b);
    return *(unsigned*)&t;
}

// fp32 pair -> bf16x2 (lo=a, hi=b), same rn rounding as pk()
__device__ __forceinline__ unsigned cvt2(float lo, float hi) {
    unsigned r;
    asm("cvt.rn.bf16x2.f32 %0, %1, %2;" : "=r"(r) : "f"(hi), "f"(lo));
    return r;
}

// pair-layout column permutation: kk -> col' within each 8-word k-group
__device__ __host__ __forceinline__ int permc(int kk) {
    return (kk & ~7) + 2 * (kk & 3) + ((kk >> 2) & 1);
}

__device__ __forceinline__ void mma_bf16(float c[4], const unsigned a[4], const unsigned b[2]) {
    asm volatile(
        "mma.sync.aligned.m16n8k16.row.col.f32.bf16.bf16.f32 "
        "{%0,%1,%2,%3},{%4,%5,%6,%7},{%8,%9},{%0,%1,%2,%3};\n"
        : "+f"(c[0]), "+f"(c[1]), "+f"(c[2]), "+f"(c[3])
        : "r"(a[0]), "r"(a[1]), "r"(a[2]), "r"(a[3]), "r"(b[0]), "r"(b[1]));
}

#define CP_ASYNC16(dst, src) \
    asm volatile("cp.async.cg.shared.global [%0], [%1], 16;" :: "r"(dst), "l"(src))
#define CP_COMMIT() asm volatile("cp.async.commit_group;" ::)
#define CP_WAIT0()  asm volatile("cp.async.wait_group 0;" ::)

// 32xN(=128)xK(=128) block-GEMM step (OLD layouts; used by kt_mma only)
__device__ __forceinline__ void gemm32(const unsigned* sA, int astride,
                                       const unsigned* sB, int mg, int ng,
                                       int lane, float acc[4][4]) {
    const int g = lane >> 2, q = lane & 3;
#pragma unroll
    for (int s = 0; s < 8; ++s) {
        unsigned a[4], bf[4][2];
        const unsigned* base = sA + (mg * 16 + g) * astride + s * 8 + q;
        a[0] = base[0];
        a[1] = base[8 * astride];
        a[2] = base[4];
        a[3] = base[8 * astride + 4];
#pragma unroll
        for (int t = 0; t < 4; ++t) {
            int n = ng * 32 + t * 8 + g;
            bf[t][0] = sB[(s * 8 + q) * 136 + n];
            bf[t][1] = sB[(s * 8 + 4 + q) * 136 + n];
        }
#pragma unroll
        for (int t = 0; t < 4; ++t) mma_bf16(acc[t], a, bf[t]);
    }
}

// =================== Kprep: pack ALL weights to bf16x2 =====================
__global__ __launch_bounds__(256)
void k_prep(const float* __restrict__ W1, const float* __restrict__ W2,
            const float* __restrict__ W3, const float* __restrict__ Wd1,
            const float* __restrict__ Wd2) {
    int idx = blockIdx.x * 256 + threadIdx.x;
    if (idx < 24576) {                       // g_Wp1: 6 tiles x 4096 (pair layout)
        int kt = idx >> 12;
        int r = idx & 4095;
        int s = r >> 10;
        int n = (r >> 3) & 127;
        int q = (r >> 1) & 3;
        int which = r & 1;
        int kk = kt * 32 + s * 8 + q + 4 * which;
        g_Wp1[idx] = pk(W1[(size_t)n * 512 + 128 + 2 * kk],
                        W1[(size_t)n * 512 + 128 + 2 * kk + 1]);
    } else if (idx < 32768) {                // g_Wp2: 2 tiles x 4096 (pair layout)
        int j = idx - 24576;
        int kt = j >> 12;
        int r = j & 4095;
        int s = r >> 10;
        int n = (r >> 3) & 127;
        int q = (r >> 1) & 3;
        int which = r & 1;
        int kk = kt * 32 + s * 8 + q + 4 * which;
        g_Wp2[j] = pk(W2[(size_t)n * 128 + 2 * kk],
                      W2[(size_t)n * 128 + 2 * kk + 1]);
    } else if (idx < 40960) {                // g_Wp3: 64*128 (old style)
        int j = idx - 32768;
        int kk = j >> 7, d = j & 127;
        g_Wp3[j] = pk(W3[(size_t)d * 128 + 2 * kk],
                      W3[(size_t)d * 128 + 2 * kk + 1]);
    } else if (idx < 73728) {                // g_WpD1: 256*128 (old style)
        int j = idx - 40960;
        int row = j >> 7, hh = j & 127;
        int t = row >> 6, kk = row & 63;
        g_WpD1[j] = pk(Wd1[(size_t)(t * 128 + hh) * 128 + 2 * kk],
                       Wd1[(size_t)(t * 128 + hh) * 128 + 2 * kk + 1]);
    } else if (idx < 106496) {               // g_WpD2: 256*128 (old style)
        int j = idx - 73728;
        int row = j >> 7, c = j & 127;
        int kt = row >> 6, kk = row & 63;
        g_WpD2[j] = pk(Wd2[(size_t)c * 512 + kt * 128 + 2 * kk],
                       Wd2[(size_t)c * 512 + kt * 128 + 2 * kk + 1]);
    }
}

// ======================= K0: node_pre = node @ W1a^T + b1 ==================
__global__ __launch_bounds__(256)
void k0_node_pre(const float* __restrict__ node, const float* __restrict__ W1,
                 const float* __restrict__ b1) {
    extern __shared__ float sm[];
    float* sX = sm;           // 32*128
    float* sW = sm + 4096;    // 128*128  sW[k][c] = W1[c*512 + k]
    const int tid = threadIdx.x, tx = tid & 15, ty = tid >> 4;
    const int n0 = blockIdx.x * 32;

#pragma unroll
    for (int m = 0; m < 4; ++m) {
        int f4 = tid + 256 * m;
        int r = f4 >> 5, c4 = f4 & 31;
        *(float4*)(sX + r * 128 + c4 * 4) =
            *(const float4*)(node + (size_t)(n0 + r) * 128 + c4 * 4);
    }
#pragma unroll
    for (int m = 0; m < 16; ++m) {
        int idx = tid + 256 * m;
        int c = idx & 127, k4 = idx >> 7;
        float4 v = *(const float4*)(W1 + (size_t)c * 512 + k4 * 4);
        sW[(k4 * 4 + 0) * 128 + c] = v.x;
        sW[(k4 * 4 + 1) * 128 + c] = v.y;
        sW[(k4 * 4 + 2) * 128 + c] = v.z;
        sW[(k4 * 4 + 3) * 128 + c] = v.w;
    }
    __syncthreads();

    float acc[2][8] = {};
#pragma unroll
    for (int kk = 0; kk < 128; kk += 4) {
        float a[2][4];
#pragma unroll
        for (int i = 0; i < 2; ++i) {
            float4 t = *(float4*)(sX + (ty + 16 * i) * 128 + kk);
            a[i][0] = t.x; a[i][1] = t.y; a[i][2] = t.z; a[i][3] = t.w;
        }
#pragma unroll
        for (int q = 0; q < 4; ++q) {
            float4 b0 = *(float4*)(sW + (kk + q) * 128 + tx * 8);
            float4 b1v = *(float4*)(sW + (kk + q) * 128 + tx * 8 + 4);
            float bb[8] = {b0.x, b0.y, b0.z, b0.w, b1v.x, b1v.y, b1v.z, b1v.w};
#pragma unroll
            for (int i = 0; i < 2; ++i)
#pragma unroll
                for (int j = 0; j < 8; ++j) acc[i][j] += a[i][q] * bb[j];
        }
    }
#pragma unroll
    for (int i = 0; i < 2; ++i) {
        int r = n0 + ty + 16 * i;
#pragma unroll
        for (int j = 0; j < 8; ++j) {
            int c = tx * 8 + j;
            g_node_pre[(size_t)r * 128 + c] = acc[i][j] + b1[c];
        }
    }
}

// ================ K1: per-node-pair edge message kernel (bf16 MMA) =========
// A tiles: cp.async fp32 direct to smem (stride 72, conflict-free), bf16
// conversion fused into fragment load (cvt.rn.bf16x2.f32 — same rounding).
// B tiles: cp.async pair layout (R15). Double-buffered. sH aliases dead A.
#define A0_OFF 0            // 96*72 fp32
#define A1_OFF 6912
#define B0_OFF 13824        // 4096 pair tile
#define B1_OFF 17920
#define SH1_OFF 0           // 96*72 bf16x2 (aliases A0; A dead after GEMM1)
#define NP_OFF 22016        // 256 f
#define AT_OFF 22272        // 128 f
#define B2A_OFF 22400       // 128 f
#define S1_WORDS 22528

__global__ __launch_bounds__(256, 2)
void k1_edges(const float* __restrict__ edge, const float* __restrict__ attn,
              const float* __restrict__ b2) {
    extern __shared__ unsigned smu[];
    unsigned* sH = smu + SH1_OFF;
    float* sNP = (float*)(smu + NP_OFF);
    float* sAt = (float*)(smu + AT_OFF);
    float* sb2 = (float*)(smu + B2A_OFF);
    const unsigned smem_base = (unsigned)__cvta_generic_to_shared(smu);

    const int tid = threadIdx.x;
    const int lane = tid & 31, wid = tid >> 5;
    const int mg = wid >> 2;
    const int ng = wid & 3;
    const int g = lane >> 2, q = lane & 3;
    const int n0 = blockIdx.x * 2;
    const float* eb = edge + (size_t)n0 * (KN * EC);

    sNP[tid] = g_node_pre[(size_t)n0 * 128 + tid];
    if (tid < 96) sAt[tid] = attn[(size_t)n0 * KN + tid];
    if (tid < 128) sb2[tid] = b2[tid];

    // ---- prologue: tile 0 (A fp32 + B) fully via cp.async ----
#pragma unroll
    for (int m = 0; m < 6; ++m) {
        int f = tid + 256 * m;                 // 0..1535 chunks of 16B
        int row = f >> 4, col = f & 15;        // col: 16B chunk (4 floats)
        CP_ASYNC16(smem_base + (A0_OFF + row * 72 + col * 4) * 4,
                   eb + (size_t)row * EC + col * 4);
    }
#pragma unroll
    for (int m = 0; m < 4; ++m) {
        int f = tid + 256 * m;
        CP_ASYNC16(smem_base + (B0_OFF + f * 4) * 4, g_Wp1 + f * 4);
    }
    CP_COMMIT();
    CP_WAIT0();
    __syncthreads();

    float acc[3][4][4] = {};

    // ---------------- GEMM1b: 6 double-buffered k-tiles of 64 --------------
    for (int kt = 0; kt < 6; ++kt) {
        const unsigned* sA = smu + ((kt & 1) ? A1_OFF : A0_OFF);
        const unsigned* sB = smu + ((kt & 1) ? B1_OFF : B0_OFF);
        if (kt < 5) {
            unsigned adst = smem_base + (((kt + 1) & 1) ? A1_OFF : A0_OFF) * 4;
            unsigned bdst = smem_base + (((kt + 1) & 1) ? B1_OFF : B0_OFF) * 4;
#pragma unroll
            for (int m = 0; m < 6; ++m) {
                int f = tid + 256 * m;
                int row = f >> 4, col = f & 15;
                CP_ASYNC16(adst + (row * 72 + col * 4) * 4,
                           eb + (size_t)row * EC + (kt + 1) * 64 + col * 4);
            }
#pragma unroll
            for (int m = 0; m < 4; ++m) {
                int f = tid + 256 * m;
                CP_ASYNC16(bdst + f * 16, g_Wp1 + (size_t)(kt + 1) * 4096 + f * 4);
            }
            CP_COMMIT();
        } else {
            // prefetch W2 pair-tile 0 into B0 (free since kt=4)
#pragma unroll
            for (int m = 0; m < 4; ++m) {
                int f = tid + 256 * m;
                CP_ASYNC16(smem_base + (B0_OFF + f * 4) * 4, g_Wp2 + f * 4);
            }
            CP_COMMIT();
        }
#pragma unroll
        for (int s = 0; s < 4; ++s) {
            unsigned a[3][4];
            uint2 bf[4];
#pragma unroll
            for (int mi = 0; mi < 3; ++mi) {
                const float* base = (const float*)sA +
                                    (mg * 48 + mi * 16 + g) * 72 + s * 16 + 2 * q;
                float2 p0 = *(const float2*)base;
                float2 p1 = *(const float2*)(base + 8);
                float2 p2 = *(const float2*)(base + 8 * 72);
                float2 p3 = *(const float2*)(base + 8 * 72 + 8);
                a[mi][0] = cvt2(p0.x, p0.y);
                a[mi][2] = cvt2(p1.x, p1.y);
                a[mi][1] = cvt2(p2.x, p2.y);
                a[mi][3] = cvt2(p3.x, p3.y);
            }
#pragma unroll
            for (int t = 0; t < 4; ++t)
                bf[t] = *(const uint2*)(sB + s * 1024 + (ng * 32 + t * 8 + g) * 8 + q * 2);
#pragma unroll
            for (int mi = 0; mi < 3; ++mi)
#pragma unroll
                for (int t = 0; t < 4; ++t) mma_bf16(acc[mi][t], a[mi], &bf[t].x);
        }
        CP_WAIT0();
        __syncthreads();
    }

    // ---- epilogue 1: kick W2 pair-tile 1 -> B1; h1 = gelu(node_pre+acc) ----
    // sH aliases A0/A1 region — all GEMM1 A reads completed above.
#pragma unroll
    for (int m = 0; m < 4; ++m) {
        int f = tid + 256 * m;
        CP_ASYNC16(smem_base + (B1_OFF + f * 4) * 4, g_Wp2 + 4096 + f * 4);
    }
    CP_COMMIT();
#pragma unroll
    for (int mi = 0; mi < 3; ++mi) {
        int r0 = mg * 48 + mi * 16 + g;
#pragma unroll
        for (int t = 0; t < 4; ++t) {
            int c = ng * 32 + t * 8 + 2 * q;
            float np0 = sNP[mg * 128 + c], np1 = sNP[mg * 128 + c + 1];
            unsigned lo = pk(gelu_f(acc[mi][t][0] + np0), gelu_f(acc[mi][t][1] + np1));
            unsigned hi = pk(gelu_f(acc[mi][t][2] + np0), gelu_f(acc[mi][t][3] + np1));
            int pw = permc(ng * 16 + t * 4 + q);
            sH[r0 * 72 + pw] = lo;
            sH[(r0 + 8) * 72 + pw] = hi;
            acc[mi][t][0] = acc[mi][t][1] = acc[mi][t][2] = acc[mi][t][3] = 0.f;
        }
    }
    if (tid < 2) {
        float s = 0.f;
#pragma unroll
        for (int k = 0; k < KN; ++k) s += sAt[tid * KN + k];
        g_A[n0 + tid] = s;
    }
    CP_WAIT0();
    __syncthreads();

    // ---------------- GEMM2: h1 @ W2^T (8 k16 steps, B0 then B1) -----------
#pragma unroll
    for (int s = 0; s < 8; ++s) {
        const unsigned* sBp = smu + ((s < 4) ? B0_OFF : B1_OFF);
        int ss = s & 3;
        unsigned a[3][4];
        uint2 bf[4];
#pragma unroll
        for (int mi = 0; mi < 3; ++mi) {
            const unsigned* base = sH + (mg * 48 + mi * 16 + g) * 72 + s * 8 + 2 * q;
            uint2 va = *(const uint2*)base;
            uint2 vb = *(const uint2*)(base + 8 * 72);
            a[mi][0] = va.x; a[mi][2] = va.y;
            a[mi][1] = vb.x; a[mi][3] = vb.y;
        }
#pragma unroll
        for (int t = 0; t < 4; ++t)
            bf[t] = *(const uint2*)(sBp + ss * 1024 + (ng * 32 + t * 8 + g) * 8 + q * 2);
#pragma unroll
        for (int mi = 0; mi < 3; ++mi)
#pragma unroll
            for (int t = 0; t < 4; ++t) mma_bf16(acc[mi][t], a[mi], &bf[t].x);
    }

    // ---- epilogue 2: gelu(+b2), attn-weighted reduce over the 48 rows -----
#pragma unroll
    for (int t = 0; t < 4; ++t) {
        int c = ng * 32 + t * 8 + 2 * q;
        float bc0 = sb2[c], bc1 = sb2[c + 1];
        float p0 = 0.f, p1 = 0.f;
#pragma unroll
        for (int mi = 0; mi < 3; ++mi) {
            int r0 = mi * 16 + g;
            float w0 = sAt[mg * 48 + r0];
            float w1 = sAt[mg * 48 + r0 + 8];
            p0 += w0 * gelu_f(acc[mi][t][0] + bc0) + w1 * gelu_f(acc[mi][t][2] + bc0);
            p1 += w0 * gelu_f(acc[mi][t][1] + bc1) + w1 * gelu_f(acc[mi][t][3] + bc1);
        }
#pragma unroll
        for (int off = 16; off >= 4; off >>= 1) {
            p0 += __shfl_xor_sync(0xffffffffu, p0, off);
            p1 += __shfl_xor_sync(0xffffffffu, p1, off);
        }
        if (lane < 4) {
            int cc = ng * 32 + t * 8 + 2 * lane;
            g_S[(size_t)(n0 + mg) * 128 + cc] = p0;
            g_S[(size_t)(n0 + mg) * 128 + cc + 1] = p1;
        }
    }
}

// ============== KT: fused bf16-MMA tail, 32 nodes/block, grid 128 ==========
#define T_SB   0
#define T_AB   8704
#define T_HB   10880
#define T_RES  19200
#define T_SX   23424
#define T_RED  27648
#define T_WORDS 28672

__global__ __launch_bounds__(256)
void kt_mma(const float* __restrict__ node, const float* __restrict__ b3,
            const float* __restrict__ g1, const float* __restrict__ be1,
            const float* __restrict__ bd1, const float* __restrict__ bd2,
            const float* __restrict__ g2, const float* __restrict__ be2,
            const float* __restrict__ maskp, float* __restrict__ out) {
    extern __shared__ unsigned smu[];
    unsigned* sB = smu + T_SB;
    unsigned* sAb = smu + T_AB;
    unsigned* sHb = smu + T_HB;
    float* sRes = (float*)(smu + T_RES);
    float* sX = (float*)(smu + T_SX);
    float* sRed = (float*)(smu + T_RED);

    const int tid = threadIdx.x;
    const int lane = tid & 31, wid = tid >> 5;
    const int mg = wid >> 2, ng = wid & 3;
    const int g = lane >> 2, q = lane & 3;
    const int tx = tid & 15, ty = tid >> 4;
    const int n0 = blockIdx.x * 32;

#pragma unroll
    for (int m = 0; m < 4; ++m) {
        int f = tid + 256 * m;
        int row = f >> 5, c4 = f & 31;
        float4 v = *(const float4*)(g_S + (size_t)(n0 + row) * 128 + c4 * 4);
        *(uint2*)(sAb + row * 68 + c4 * 2) = make_uint2(pk(v.x, v.y), pk(v.z, v.w));
    }
#pragma unroll
    for (int m = 0; m < 8; ++m) {
        int f = tid + 256 * m;
        int kk = f >> 5, c4 = f & 31;
        *(uint4*)(sB + kk * 136 + c4 * 4) =
            *(const uint4*)(g_Wp3 + (size_t)kk * 128 + c4 * 4);
    }
    __syncthreads();

    float acc[4][4] = {};
    gemm32(sAb, 68, sB, mg, ng, lane, acc);
    {
        int r0 = mg * 16 + g;
#pragma unroll
        for (int t = 0; t < 4; ++t) {
            int c = ng * 32 + t * 8 + 2 * q;
            sRes[r0 * 132 + c] = acc[t][0];
            sRes[r0 * 132 + c + 1] = acc[t][1];
            sRes[(r0 + 8) * 132 + c] = acc[t][2];
            sRes[(r0 + 8) * 132 + c + 1] = acc[t][3];
        }
    }
    __syncthreads();

    float xv[2][8];
#pragma unroll
    for (int i = 0; i < 2; ++i) {
        int r = ty + 16 * i, n = n0 + r;
        float As = g_A[n];
        float s = 0.f, qs = 0.f;
#pragma unroll
        for (int j = 0; j < 8; ++j) {
            int c = tx * 8 + j;
            float v = node[(size_t)n * 128 + c] +
                      (sRes[r * 132 + c] + As * b3[c]) * (1.0f / 30.0f);
            xv[i][j] = v; s += v; qs += v * v;
        }
        sRed[r * 16 + tx] = s;
        sRed[512 + r * 16 + tx] = qs;
    }
    __syncthreads();
#pragma unroll
    for (int i = 0; i < 2; ++i) {
        int r = ty + 16 * i;
        float s = 0.f, qs = 0.f;
#pragma unroll
        for (int t = 0; t < 16; ++t) {
            s += sRed[r * 16 + t];
            qs += sRed[512 + r * 16 + t];
        }
        float mu = s * (1.0f / 128.0f);
        float var = qs * (1.0f / 128.0f) - mu * mu;
        float rs = rsqrtf(var + 1e-5f);
        float o[8];
#pragma unroll
        for (int j = 0; j < 8; ++j) {
            int c = tx * 8 + j;
            o[j] = (xv[i][j] - mu) * rs * g1[c] + be1[c];
            sX[r * 132 + c] = o[j];
        }
#pragma unroll
        for (int m = 0; m < 4; ++m)
            sAb[r * 68 + tx * 4 + m] = pk(o[2 * m], o[2 * m + 1]);
    }

    for (int t = 0; t < 4; ++t) {
        __syncthreads();
#pragma unroll
        for (int m = 0; m < 8; ++m) {
            int f = tid + 256 * m;
            int kk = f >> 5, c4 = f & 31;
            *(uint4*)(sB + kk * 136 + c4 * 4) =
                *(const uint4*)(g_WpD1 + (size_t)(t * 64 + kk) * 128 + c4 * 4);
        }
        __syncthreads();
        float a2[4][4] = {};
        gemm32(sAb, 68, sB, mg, ng, lane, a2);
        int r0 = mg * 16 + g;
#pragma unroll
        for (int tp = 0; tp < 4; ++tp) {
            int cl = ng * 32 + tp * 8 + 2 * q;
            int h = t * 128 + cl;
            float bb0 = bd1[h], bb1 = bd1[h + 1];
            unsigned lo = pk(gelu_f(a2[tp][0] + bb0), gelu_f(a2[tp][1] + bb1));
            unsigned hi = pk(gelu_f(a2[tp][2] + bb0), gelu_f(a2[tp][3] + bb1));
            int widx = t * 64 + ng * 16 + tp * 4 + q;
            sHb[r0 * 260 + widx] = lo;
            sHb[(r0 + 8) * 260 + widx] = hi;
        }
    }

    float acc3[4][4] = {};
    for (int kt = 0; kt < 4; ++kt) {
        __syncthreads();
#pragma unroll
        for (int m = 0; m < 8; ++m) {
            int f = tid + 256 * m;
            int kk = f >> 5, c4 = f & 31;
            *(uint4*)(sB + kk * 136 + c4 * 4) =
                *(const uint4*)(g_WpD2 + (size_t)(kt * 64 + kk) * 128 + c4 * 4);
        }
        __syncthreads();
        gemm32(sHb + kt * 64, 260, sB, mg, ng, lane, acc3);
    }
    {
        int r0 = mg * 16 + g;
#pragma unroll
        for (int t = 0; t < 4; ++t) {
            int c = ng * 32 + t * 8 + 2 * q;
            sRes[r0 * 132 + c] = acc3[t][0];
            sRes[r0 * 132 + c + 1] = acc3[t][1];
            sRes[(r0 + 8) * 132 + c] = acc3[t][2];
            sRes[(r0 + 8) * 132 + c + 1] = acc3[t][3];
        }
    }
    __syncthreads();

    float vv[2][8];
#pragma unroll
    for (int i = 0; i < 2; ++i) {
        int r = ty + 16 * i;
        float s = 0.f, qs = 0.f;
#pragma unroll
        for (int j = 0; j < 8; ++j) {
            int c = tx * 8 + j;
            float v = sX[r * 132 + c] + sRes[r * 132 + c] + bd2[c];
            vv[i][j] = v; s += v; qs += v * v;
        }
        sRed[r * 16 + tx] = s;
        sRed[512 + r * 16 + tx] = qs;
    }
    __syncthreads();
#pragma unroll
    for (int i = 0; i < 2; ++i) {
        int r = ty + 16 * i, n = n0 + r;
        float s = 0.f, qs = 0.f;
#pragma unroll
        for (int t = 0; t < 16; ++t) {
            s += sRed[r * 16 + t];
            qs += sRed[512 + r * 16 + t];
        }
        float mu = s * (1.0f / 128.0f);
        float var = qs * (1.0f / 128.0f) - mu * mu;
        float rs = rsqrtf(var + 1e-5f);
        float mk = maskp[n];
        float o[8];
#pragma unroll
        for (int j = 0; j < 8; ++j) {
            int c = tx * 8 + j;
            o[j] = mk * ((vv[i][j] - mu) * rs * g2[c] + be2[c]);
        }
        *(float4*)(out + (size_t)n * 128 + tx * 8) = make_float4(o[0], o[1], o[2], o[3]);
        *(float4*)(out + (size_t)n * 128 + tx * 8 + 4) = make_float4(o[4], o[5], o[6], o[7]);
    }
}

// ============================== launch =====================================
extern "C" void kernel_launch(void* const* d_in, const int* in_sizes, int n_in,
                              void* d_out, int out_size) {
    const float* node = (const float*)d_in[0];
    const float* edge = (const float*)d_in[1];
    const float* mask = (const float*)d_in[2];
    const float* attn = (const float*)d_in[3];
    const float* W1   = (const float*)d_in[4];
    const float* b1   = (const float*)d_in[5];
    const float* W2   = (const float*)d_in[6];
    const float* b2   = (const float*)d_in[7];
    const float* W3   = (const float*)d_in[8];
    const float* b3   = (const float*)d_in[9];
    const float* g1   = (const float*)d_in[10];
    const float* be1  = (const float*)d_in[11];
    const float* Wd1  = (const float*)d_in[12];
    const float* bd1  = (const float*)d_in[13];
    const float* Wd2  = (const float*)d_in[14];
    const float* bd2  = (const float*)d_in[15];
    const float* g2   = (const float*)d_in[16];
    const float* be2  = (const float*)d_in[17];
    float* out = (float*)d_out;

    const size_t s0 = (size_t)(4096 + 16384) * sizeof(float);
    const size_t s1 = (size_t)S1_WORDS * sizeof(unsigned);
    const size_t st = (size_t)T_WORDS * sizeof(unsigned);

    cudaFuncSetAttribute(k0_node_pre, cudaFuncAttributeMaxDynamicSharedMemorySize, (int)s0);
    cudaFuncSetAttribute(k1_edges,    cudaFuncAttributeMaxDynamicSharedMemorySize, (int)s1);
    cudaFuncSetAttribute(kt_mma,      cudaFuncAttributeMaxDynamicSharedMemorySize, (int)st);

    k_prep<<<416, 256>>>(W1, W2, W3, Wd1, Wd2);
    k0_node_pre<<<NN / 32, 256, s0>>>(node, W1, b1);
    k1_edges<<<NN / 2, 256, s1>>>(edge, attn, b2);
    kt_mma<<<NN / 32, 256, st>>>(node, b3, g1, be1, bd1, bd2, g2, be2, mask, out);
}